// round 4
// baseline (speedup 1.0000x reference)
#include <cuda_runtime.h>
#include <math.h>
#include <float.h>
#include <stdint.h>

// Problem constants
#define H_   248
#define W_   216
#define HW   (H_*W_)          // 53568
#define NANCH 6
#define NTOT (HW*NANCH)       // 321408 rows per batch
#define BSZ  16
#define NPRE 100
#define MAXN 50
#define NBINS 2048
#define CAP   3072

// Scratch (static device allocations are allowed)
__device__ float g_score[BSZ][NTOT];   // max logit per row, layout j = a*HW + s
__device__ int   g_hist[BSZ][NBINS];
__device__ int   g_top[BSZ][NPRE];     // original row index i = s*6 + a, descending score order

__device__ __forceinline__ unsigned fkey(float v) {
    unsigned b = __float_as_uint(v);
    return (b & 0x80000000u) ? ~b : (b | 0x80000000u); // monotone float->uint
}

// ---------------------------------------------------------------------------
__global__ void k_zero_hist() {
    int i = blockIdx.x * blockDim.x + threadIdx.x;
    if (i < BSZ * NBINS) ((int*)g_hist)[i] = 0;
}

// Pass 1: max-logit per anchor row + per-batch histogram of key top-11 bits
__global__ void k_score(const float* __restrict__ cls) {
    __shared__ int sh[NBINS];
    for (int i = threadIdx.x; i < NBINS; i += blockDim.x) sh[i] = 0;
    __syncthreads();

    int b = blockIdx.y;
    int j = blockIdx.x * blockDim.x + threadIdx.x; // j = a*HW + s
    if (j < NTOT) {
        int a = j / HW, s = j - a * HW;
        const float* base = cls + (size_t)b * 18 * HW + (size_t)(3 * a) * HW + s;
        float v0 = base[0];
        float v1 = base[HW];
        float v2 = base[2 * HW];
        float m = fmaxf(v0, fmaxf(v1, v2));
        g_score[b][j] = m;
        atomicAdd(&sh[fkey(m) >> 21], 1);
    }
    __syncthreads();
    for (int i = threadIdx.x; i < NBINS; i += blockDim.x)
        if (sh[i]) atomicAdd(&g_hist[b][i], sh[i]);
}

// Pass 2: per batch — threshold bin from histogram, collect candidates,
// exact ordered top-100 by (value desc, index asc)  [matches lax.top_k]
__global__ void k_select() {
    int b   = blockIdx.x;
    int tid = threadIdx.x;

    __shared__ float cv[CAP];
    __shared__ int   ci[CAP];
    __shared__ float rv[1024];
    __shared__ int   ri[1024];
    __shared__ int   rs[1024];
    __shared__ int   s_t, s_c;

    if (tid == 0) {
        int acc = 0, t = 0;
        for (int k = NBINS - 1; k >= 0; k--) {
            acc += g_hist[b][k];
            if (acc >= NPRE) { t = k; break; }
        }
        s_t = t;
        s_c = 0;
    }
    __syncthreads();
    unsigned t = (unsigned)s_t;

    for (int j = tid; j < NTOT; j += blockDim.x) {
        float v = g_score[b][j];
        if ((fkey(v) >> 21) >= t) {
            int slot = atomicAdd(&s_c, 1);
            if (slot < CAP) {
                cv[slot] = v;
                int a = j / HW, s = j - a * HW;
                ci[slot] = s * 6 + a; // original reshaped row index
            }
        }
    }
    __syncthreads();
    int C = min(s_c, CAP); // >= 100 by construction

    for (int k = 0; k < NPRE; k++) {
        float bv = -FLT_MAX; int bi = 0x7fffffff, bsl = -1;
        for (int u = tid; u < C; u += blockDim.x) {
            float v = cv[u]; int idx = ci[u];
            if (v > bv || (v == bv && idx < bi)) { bv = v; bi = idx; bsl = u; }
        }
        rv[tid] = bv; ri[tid] = bi; rs[tid] = bsl;
        __syncthreads();
        for (int off = blockDim.x / 2; off > 0; off >>= 1) {
            if (tid < off) {
                float v2 = rv[tid + off]; int i2 = ri[tid + off];
                if (v2 > rv[tid] || (v2 == rv[tid] && i2 < ri[tid])) {
                    rv[tid] = v2; ri[tid] = i2; rs[tid] = rs[tid + off];
                }
            }
            __syncthreads();
        }
        if (tid == 0) {
            g_top[b][k] = ri[0];
            if (rs[0] >= 0) cv[rs[0]] = -FLT_MAX; // consume winner
        }
        __syncthreads();
    }
}

// Pass 3: per batch — gather/decode 100 boxes, per-class NMS (3 warps),
// final ordered top-50, write outputs.
__global__ void k_final(const float* __restrict__ cls,
                        const float* __restrict__ box,
                        const float* __restrict__ dir,
                        const float* __restrict__ anc,
                        float* __restrict__ out) {
    int b   = blockIdx.x;
    int tid = threadIdx.x;

    __shared__ float bb[NPRE][7];
    __shared__ float b2d[NPRE][4];
    __shared__ float area[NPRE];
    __shared__ float sc3[3][NPRE];
    __shared__ float kv[3][NPRE];
    __shared__ int   ordc[3][NPRE];
    __shared__ int   keepS[3][NPRE];   // sorted-order keep flags
    __shared__ int   keepP[3][NPRE];   // position-order keep flags
    __shared__ float fv[3 * NPRE];

    const float PI = 3.14159265358979323846f;

    if (tid < NPRE) {
        int i = g_top[b][tid];
        int s = i / 6, a = i - 6 * s;

        const float* cb = cls + (size_t)b * 18 * HW + s;
        #pragma unroll
        for (int c = 0; c < 3; c++) {
            float x = cb[(size_t)(3 * a + c) * HW];
            sc3[c][tid] = 0.5f * tanhf(0.5f * x) + 0.5f; // sigmoid, XLA-style
        }

        const float* pb = box + (size_t)b * 42 * HW + s;
        float d[7];
        #pragma unroll
        for (int j = 0; j < 7; j++) d[j] = pb[(size_t)(7 * a + j) * HW];

        const float* db = dir + (size_t)b * 12 * HW + s;
        float d0 = db[(size_t)(2 * a) * HW];
        float d1 = db[(size_t)(2 * a + 1) * HW];
        int dircls = (d1 > d0) ? 1 : 0; // argmax, ties -> 0

        const float* ab = anc + (size_t)i * 7;
        float xa = ab[0], ya = ab[1], za = ab[2];
        float wa = ab[3], la = ab[4], ha = ab[5], ra = ab[6];

        float da = sqrtf(wa * wa + la * la);
        float x = d[0] * da + xa;
        float y = d[1] * da + ya;
        float z = d[2] * ha + za + ha * 0.5f;
        float w = wa * expf(d[3]);
        float l = la * expf(d[4]);
        float h = ha * expf(d[5]);
        z = z - h * 0.5f;
        float th0 = ra + d[6];
        float lp  = th0 - floorf(th0 / PI + 1.0f) * PI;
        float th  = lp + (1.0f - (float)dircls) * PI;

        bb[tid][0] = x; bb[tid][1] = y; bb[tid][2] = z;
        bb[tid][3] = w; bb[tid][4] = l; bb[tid][5] = h; bb[tid][6] = th;

        float x1 = x - w * 0.5f, y1 = y - l * 0.5f;
        float x2 = x + w * 0.5f, y2 = y + l * 0.5f;
        b2d[tid][0] = x1; b2d[tid][1] = y1; b2d[tid][2] = x2; b2d[tid][3] = y2;
        area[tid] = (x2 - x1) * (y2 - y1);
    }
    __syncthreads();

    int wp = tid >> 5, lane = tid & 31;
    if (wp < 3) {
        int c = wp;
        // keys: valid ? score : -inf  (stable argsort desc == (v desc, idx asc))
        for (int tt = lane; tt < NPRE; tt += 32) {
            float s = sc3[c][tt];
            kv[c][tt] = (s > 0.1f) ? s : -FLT_MAX;
        }
        __syncwarp();
        for (int tt = lane; tt < NPRE; tt += 32) {
            float v = kv[c][tt];
            int r = 0;
            #pragma unroll 4
            for (int u = 0; u < NPRE; u++) {
                float vu = kv[c][u];
                r += (vu > v) || (vu == v && u < tt);
            }
            ordc[c][r] = tt;
        }
        __syncwarp();
        for (int rr = lane; rr < NPRE; rr += 32)
            keepS[c][rr] = (kv[c][ordc[c][rr]] != -FLT_MAX) ? 1 : 0;
        __syncwarp();

        // greedy NMS (IoU > 0.01), suppression only from still-kept boxes
        for (int ii = 0; ii < NPRE - 1; ii++) {
            if (keepS[c][ii]) {
                int bi = ordc[c][ii];
                float ax1 = b2d[bi][0], ay1 = b2d[bi][1];
                float ax2 = b2d[bi][2], ay2 = b2d[bi][3];
                float aa  = area[bi];
                for (int jj = ii + 1 + lane; jj < NPRE; jj += 32) {
                    if (!keepS[c][jj]) continue;
                    int bj = ordc[c][jj];
                    float x1 = fmaxf(ax1, b2d[bj][0]);
                    float y1 = fmaxf(ay1, b2d[bj][1]);
                    float x2 = fminf(ax2, b2d[bj][2]);
                    float y2 = fminf(ay2, b2d[bj][3]);
                    float inter = fmaxf(x2 - x1, 0.0f) * fmaxf(y2 - y1, 0.0f);
                    float iou = inter / (aa + area[bj] - inter + 1e-8f);
                    if (iou > 0.01f) keepS[c][jj] = 0;
                }
            }
            __syncwarp();
        }

        for (int rr = lane; rr < NPRE; rr += 32)
            keepP[c][ordc[c][rr]] = keepS[c][rr];
        __syncwarp();
        for (int p = lane; p < NPRE; p += 32)
            fv[c * NPRE + p] = keepP[c][p] ? sc3[c][p] : -1.0f;
    }
    __syncthreads();

    // top-50 over 300 flat entries, (value desc, flat index asc) — exact top_k
    for (int e = tid; e < 3 * NPRE; e += blockDim.x) {
        float v = fv[e];
        int r = 0;
        for (int u = 0; u < 3 * NPRE; u++) {
            float vu = fv[u];
            r += (vu > v) || (vu == v && u < e);
        }
        if (r < MAXN) {
            int sel = e % NPRE;
            int lab = e / NPRE;
            // output layout: bboxes[16*50*7] | labels[800] | scores[800] | mask[800]
            float* ob = out + (size_t)b * MAXN * 7 + (size_t)r * 7;
            #pragma unroll
            for (int j = 0; j < 7; j++) ob[j] = bb[sel][j];
            out[BSZ * MAXN * 7 +                 b * MAXN + r] = (float)lab;
            out[BSZ * MAXN * 7 + BSZ * MAXN +    b * MAXN + r] = v;
            out[BSZ * MAXN * 7 + 2 * BSZ * MAXN + b * MAXN + r] = (v > 0.0f) ? 1.0f : 0.0f;
        }
    }
}

// ---------------------------------------------------------------------------
extern "C" void kernel_launch(void* const* d_in, const int* in_sizes, int n_in,
                              void* d_out, int out_size) {
    const float* cls = (const float*)d_in[0]; // (16,18,248,216)
    const float* box = (const float*)d_in[1]; // (16,42,248,216)
    const float* dir = (const float*)d_in[2]; // (16,12,248,216)
    const float* anc = (const float*)d_in[3]; // (248,216,3,2,7)
    float* out = (float*)d_out;

    k_zero_hist<<<(BSZ * NBINS + 255) / 256, 256>>>();

    dim3 g1((NTOT + 255) / 256, BSZ);
    k_score<<<g1, 256>>>(cls);

    k_select<<<BSZ, 1024>>>();

    k_final<<<BSZ, 128>>>(cls, box, dir, anc, out);
}